// round 1
// baseline (speedup 1.0000x reference)
#include <cuda_runtime.h>

#define HH   256
#define NN   32
#define LL   4096
#define BB   4
#define NCH  8
#define CLEN 512   // LL / NCH

// ---------------- device scratch (no allocations allowed) ----------------
__device__ float g_ar [HH*NN], g_ai [HH*NN];   // dA
__device__ float g_dbr[HH*NN], g_dbi[HH*NN];   // dB
__device__ float g_cr [HH*NN], g_ci [HH*NN];   // 2*C  (conj-pair folding)
__device__ float g_par[HH*NN], g_pai[HH*NN];   // dA^CLEN
__device__ float g_dcb[HH];                    // liquid scalar per h
__device__ float g_act[(size_t)BB*HH*LL];      // gelu(y) activations

// ---------------- precompute: discretization + liquid scalar -------------
__global__ void precompute_kernel(const float* __restrict__ log_dt,
                                  const float* __restrict__ w_re, const float* __restrict__ w_im,
                                  const float* __restrict__ B_re, const float* __restrict__ B_im,
                                  const float* __restrict__ C_re, const float* __restrict__ C_im)
{
    int idx = blockIdx.x * blockDim.x + threadIdx.x;   // = h*32 + n (warp-aligned per h)
    int h = idx >> 5;
    float dt = expf(log_dt[h]);
    float zr = 0.5f * dt * w_re[idx];
    float zi = 0.5f * dt * w_im[idx];
    // denom = 1 - z
    float dr = 1.f - zr, di = -zi;
    float inv = 1.f / (dr*dr + di*di);
    // dA = (1+z)/(1-z)
    float nr = 1.f + zr, ni = zi;
    float ar = (nr*dr + ni*di) * inv;
    float ai = (ni*dr - nr*di) * inv;
    // dB = dt*B/(1-z)
    float br = dt * B_re[idx], bi = dt * B_im[idx];
    float dbr = (br*dr + bi*di) * inv;
    float dbi = (bi*dr - br*di) * inv;
    // dA^CLEN via repeated squaring (CLEN = 2^9)
    float pr = ar, pi = ai;
    #pragma unroll
    for (int k = 0; k < 9; k++) { float t = pr*pr - pi*pi; pi = 2.f*pr*pi; pr = t; }

    float cr = C_re[idx], ci = C_im[idx];
    g_ar[idx] = ar;  g_ai[idx] = ai;
    g_dbr[idx] = dbr; g_dbi[idx] = dbi;
    g_cr[idx] = 2.f*cr; g_ci[idx] = 2.f*ci;
    g_par[idx] = pr; g_pai[idx] = pi;

    // liquid scalar: dCB = (2*sum Re dB) * (2*sum Re(C*dB))
    float s1 = dbr;
    float s2 = cr*dbr - ci*dbi;
    #pragma unroll
    for (int m = 16; m >= 1; m >>= 1) {
        s1 += __shfl_xor_sync(0xffffffffu, s1, m);
        s2 += __shfl_xor_sync(0xffffffffu, s2, m);
    }
    if ((threadIdx.x & 31) == 0) g_dcb[h] = 4.f * s1 * s2;
}

// ---------------- fused chunked scan + D skip + liquid + gelu ------------
__device__ __forceinline__ float gelu_tanh(float x)
{
    // jax.nn.gelu(approximate=True): 0.5x(1+tanh(sqrt(2/pi)(x+0.044715x^3)))
    float x3 = x * x * x;
    float z  = 0.7978845608028654f * fmaf(0.044715f, x3, x);
    float e  = __expf(2.f * z);
    float t  = 1.f - __fdividef(2.f, e + 1.f);   // tanh(z)
    return 0.5f * x * (1.f + t);
}

#define STEP(uv) { float nxr = fmaf(ar, xr, fmaf(-ai, xi, dbr*(uv))); \
                   float nxi = fmaf(ai, xr, fmaf( ar, xi, dbi*(uv))); \
                   xr = nxr; xi = nxi; }

__global__ void __launch_bounds__(256) scan_kernel(const float* __restrict__ u,
                                                   const float* __restrict__ Dp)
{
    extern __shared__ float sh[];
    float* u_sh  = sh;                    // LL floats
    float* carry = sh + LL;               // NCH*64
    float* initv = carry + NCH*64;        // NCH*64
    float* qbase = initv + NCH*64;        // 8 warps * 32*33

    int bid  = blockIdx.x;                // = b*HH + h
    int h    = bid & (HH-1);
    int tid  = threadIdx.x;
    int wid  = tid >> 5, lane = tid & 31;

    // stage whole sequence u[b,h,:] in SMEM
    const float4* ub4  = (const float4*)(u + (size_t)bid * LL);
    float4*       ush4 = (float4*)u_sh;
    #pragma unroll
    for (int i = tid; i < LL/4; i += 256) ush4[i] = ub4[i];

    int pidx = (h << 5) + lane;
    float ar = g_ar[pidx], ai = g_ai[pidx], dbr = g_dbr[pidx], dbi = g_dbi[pidx];
    __syncthreads();

    // ---- phase 1: chunk-local scan (zero init) -> carry state ----
    int base = wid * CLEN;
    float xr = 0.f, xi = 0.f;
    {
        const float4* uc4 = (const float4*)(u_sh + base);
        #pragma unroll 4
        for (int q = 0; q < CLEN/4; q++) {
            float4 uu = uc4[q];
            STEP(uu.x); STEP(uu.y); STEP(uu.z); STEP(uu.w);
        }
    }
    carry[wid*64 + lane]      = xr;
    carry[wid*64 + 32 + lane] = xi;
    __syncthreads();

    // ---- phase 2: warp 0 prefix-combines carries with dA^CLEN ----
    if (wid == 0) {
        float pr = g_par[pidx], pi = g_pai[pidx];
        float Xr = 0.f, Xi = 0.f;
        #pragma unroll
        for (int s = 0; s < NCH; s++) {
            initv[s*64 + lane]      = Xr;
            initv[s*64 + 32 + lane] = Xi;
            float cr_ = carry[s*64 + lane];
            float ci_ = carry[s*64 + 32 + lane];
            float nXr = fmaf(pr, Xr, fmaf(-pi, Xi, cr_));
            float nXi = fmaf(pi, Xr, fmaf( pr, Xi, ci_));
            Xr = nXr; Xi = nXi;
        }
    }
    __syncthreads();

    // ---- phase 3: rescan with true init, emit gelu(y) ----
    float c2r = g_cr[pidx], c2i = g_ci[pidx];
    float Dh  = Dp[h];
    float dcb = g_dcb[h];
    xr = initv[wid*64 + lane];
    xi = initv[wid*64 + 32 + lane];
    float* q    = qbase + wid * (32*33);
    float* gout = g_act + (size_t)bid * LL + base;

    for (int t0 = 0; t0 < CLEN; t0 += 32) {
        const float4* up4 = (const float4*)(u_sh + base + t0);
        #pragma unroll
        for (int jj = 0; jj < 8; jj++) {
            float4 uu = up4[jj];
            STEP(uu.x); q[(jj*4+0)*33 + lane] = fmaf(c2r, xr, -c2i*xi);
            STEP(uu.y); q[(jj*4+1)*33 + lane] = fmaf(c2r, xr, -c2i*xi);
            STEP(uu.z); q[(jj*4+2)*33 + lane] = fmaf(c2r, xr, -c2i*xi);
            STEP(uu.w); q[(jj*4+3)*33 + lane] = fmaf(c2r, xr, -c2i*xi);
        }
        __syncwarp();
        // lane j sums over states n (row j, stride-33 -> conflict-free)
        float s = 0.f;
        #pragma unroll
        for (int n = 0; n < 32; n++) s += q[lane*33 + n];
        int l = base + t0 + lane;
        float uu  = u_sh[l];
        float upv = (l > 0) ? u_sh[l-1] : 0.f;
        s = fmaf(Dh, uu, s);              // D skip
        s = fmaf(dcb * uu, upv, s);       // liquid: u_t*u_{t-1} * dCB
        gout[t0 + lane] = gelu_tanh(s);
        __syncwarp();
    }
}

// ---------------- output linear: out = W @ gelu(y) + bias ----------------
__global__ void __launch_bounds__(256) gemm_kernel(const float* __restrict__ W,
                                                   const float* __restrict__ bias,
                                                   float* __restrict__ out)
{
    __shared__ float Wsh[64][16];   // [o][k]
    __shared__ float Gsh[16][64];   // [k][l]
    int bx = blockIdx.x;            // l tile (64 wide)
    int by = blockIdx.y;            // o tile (64 wide)
    int b  = blockIdx.z;
    int tid = threadIdx.x;
    int tx = tid & 15, ty = tid >> 4;
    int o0 = by * 64, l0 = bx * 64;
    const float* gact = g_act + (size_t)b * HH * LL;

    float acc[4][4] = {};
    for (int k0 = 0; k0 < HH; k0 += 16) {
        #pragma unroll
        for (int i = 0; i < 4; i++) {
            int e  = tid + i * 256;
            int o_ = e >> 4, k_ = e & 15;
            Wsh[o_][k_] = W[(o0 + o_) * HH + k0 + k_];
            int kk = e >> 6, ll = e & 63;
            Gsh[kk][ll] = gact[(size_t)(k0 + kk) * LL + l0 + ll];
        }
        __syncthreads();
        #pragma unroll
        for (int k = 0; k < 16; k++) {
            float wv[4];
            #pragma unroll
            for (int i = 0; i < 4; i++) wv[i] = Wsh[ty*4 + i][k];
            float4 g4 = *(const float4*)&Gsh[k][tx*4];
            float gv[4] = {g4.x, g4.y, g4.z, g4.w};
            #pragma unroll
            for (int i = 0; i < 4; i++)
                #pragma unroll
                for (int j = 0; j < 4; j++)
                    acc[i][j] = fmaf(wv[i], gv[j], acc[i][j]);
        }
        __syncthreads();
    }
    #pragma unroll
    for (int i = 0; i < 4; i++) {
        int o = o0 + ty*4 + i;
        float bv = bias[o];
        float4 v;
        v.x = acc[i][0] + bv; v.y = acc[i][1] + bv;
        v.z = acc[i][2] + bv; v.w = acc[i][3] + bv;
        *(float4*)&out[((size_t)(b * HH + o)) * LL + l0 + tx*4] = v;
    }
}

// ---------------------------- launch --------------------------------------
extern "C" void kernel_launch(void* const* d_in, const int* in_sizes, int n_in,
                              void* d_out, int out_size)
{
    const float* u      = (const float*)d_in[0];
    const float* log_dt = (const float*)d_in[1];
    const float* w_re   = (const float*)d_in[2];
    const float* w_im   = (const float*)d_in[3];
    const float* B_re   = (const float*)d_in[4];
    const float* B_im   = (const float*)d_in[5];
    const float* C_re   = (const float*)d_in[6];
    const float* C_im   = (const float*)d_in[7];
    const float* D      = (const float*)d_in[8];
    const float* W      = (const float*)d_in[9];
    const float* bias   = (const float*)d_in[10];
    float* out = (float*)d_out;

    precompute_kernel<<<(HH*NN)/256, 256>>>(log_dt, w_re, w_im, B_re, B_im, C_re, C_im);

    int smem = (LL + NCH*64*2 + 8*32*33) * (int)sizeof(float);   // 54272 B
    cudaFuncSetAttribute(scan_kernel, cudaFuncAttributeMaxDynamicSharedMemorySize, smem);
    scan_kernel<<<BB*HH, 256, smem>>>(u, D);

    gemm_kernel<<<dim3(LL/64, HH/64, BB), 256>>>(W, bias, out);
}

// round 2
// speedup vs baseline: 1.2313x; 1.2313x over previous
#include <cuda_runtime.h>

#define HH   256
#define NN   32
#define LL   4096
#define BB   4
#define NCH  8
#define CLEN 512   // LL / NCH

typedef unsigned long long ull;

// ---------------- device scratch (no allocations allowed) ----------------
__device__ float g_act[(size_t)BB*HH*LL];      // gelu(y) activations

// ---------------- packed f32x2 helpers ----------------
__device__ __forceinline__ ull pk(float lo, float hi) {
    ull r;
    asm("mov.b64 %0, {%1, %2};" : "=l"(r)
        : "r"(__float_as_uint(lo)), "r"(__float_as_uint(hi)));
    return r;
}
__device__ __forceinline__ void upk(ull v, float& lo, float& hi) {
    unsigned a, b;
    asm("mov.b64 {%0, %1}, %2;" : "=r"(a), "=r"(b) : "l"(v));
    lo = __uint_as_float(a); hi = __uint_as_float(b);
}
__device__ __forceinline__ ull fma2(ull a, ull b, ull c) {
    ull d;
    asm("fma.rn.f32x2 %0, %1, %2, %3;" : "=l"(d) : "l"(a), "l"(b), "l"(c));
    return d;
}
__device__ __forceinline__ ull mul2(ull a, ull b) {
    ull d;
    asm("mul.rn.f32x2 %0, %1, %2;" : "=l"(d) : "l"(a), "l"(b));
    return d;
}

__device__ __forceinline__ float gelu_tanh(float x)
{
    // jax.nn.gelu(approximate=True)
    float x3 = x * x * x;
    float z  = 0.7978845608028654f * fmaf(0.044715f, x3, x);
    float e  = __expf(2.f * z);
    float t  = 1.f - __fdividef(2.f, e + 1.f);   // tanh(z)
    return 0.5f * x * (1.f + t);
}

// ---------------- fused scan: params + chunked scan + D + liquid + gelu ---
__global__ void __launch_bounds__(256) scan_kernel(
    const float* __restrict__ u,
    const float* __restrict__ log_dt,
    const float* __restrict__ w_re, const float* __restrict__ w_im,
    const float* __restrict__ B_re, const float* __restrict__ B_im,
    const float* __restrict__ C_re, const float* __restrict__ C_im,
    const float* __restrict__ Dp)
{
    extern __shared__ float sh[];
    float* u_sh  = sh;                    // LL floats
    float* carry = sh + LL;               // NCH*64
    float* initv = carry + NCH*64;        // NCH*64
    float* qbase = initv + NCH*64;        // 8 warps * 32*33

    int bid  = blockIdx.x;                // = b*HH + h
    int h    = bid & (HH-1);
    int tid  = threadIdx.x;
    int wid  = tid >> 5, lane = tid & 31;

    // stage whole sequence u[b,h,:] in SMEM
    const float4* ub4  = (const float4*)(u + (size_t)bid * LL);
    float4*       ush4 = (float4*)u_sh;
    #pragma unroll
    for (int i = tid; i < LL/4; i += 256) ush4[i] = ub4[i];

    // ---- per-warp (redundant) parameter computation ----
    int pidx = (h << 5) + lane;
    float dt = __expf(log_dt[h]);
    float zr = 0.5f * dt * w_re[pidx];
    float zi = 0.5f * dt * w_im[pidx];
    float dr = 1.f - zr, di = -zi;
    float inv = 1.f / (dr*dr + di*di);
    float nr = 1.f + zr, ni = zi;
    float ar = (nr*dr + ni*di) * inv;
    float ai = (ni*dr - nr*di) * inv;
    float brf = dt * B_re[pidx], bif = dt * B_im[pidx];
    float dbr = (brf*dr + bif*di) * inv;
    float dbi = (bif*dr - brf*di) * inv;
    float c2r = 2.f * C_re[pidx];
    float c2i = 2.f * C_im[pidx];

    // liquid scalar dCB = 2 * (sum Re dB over 2N) ... = 2*s1*s2
    float s1 = dbr;
    float s2 = c2r*dbr - c2i*dbi;
    #pragma unroll
    for (int m = 16; m >= 1; m >>= 1) {
        s1 += __shfl_xor_sync(0xffffffffu, s1, m);
        s2 += __shfl_xor_sync(0xffffffffu, s2, m);
    }
    float dcb = 2.f * s1 * s2;

    // powers a^2, a^3, a^4 and b_k = a^k * b  for Horner-4
    float a2r = ar*ar - ai*ai,     a2i = 2.f*ar*ai;
    float a3r = a2r*ar - a2i*ai,   a3i = a2r*ai + a2i*ar;
    float a4r = a2r*a2r - a2i*a2i, a4i = 2.f*a2r*a2i;
    float b1r = ar*dbr - ai*dbi,   b1i = ar*dbi + ai*dbr;
    float b2r = a2r*dbr - a2i*dbi, b2i = a2r*dbi + a2i*dbr;
    float b3r = a3r*dbr - a3i*dbi, b3i = a3r*dbi + a3i*dbr;

    ull B0v = pk(dbr, dbi), B1v = pk(b1r, b1i);
    ull B2v = pk(b2r, b2i), B3v = pk(b3r, b3i);
    ull A4RR = pk(a4r, a4r), A4IN = pk(-a4i, a4i);
    __syncthreads();

    int base = wid * CLEN;

    // ---- phase 1: chunk-local carry via Horner-4 (last warp's carry dead) ----
    if (wid < NCH-1) {
        ull X = pk(0.f, 0.f), Xs = pk(0.f, 0.f);
        const float4* uc4 = (const float4*)(u_sh + base);
        #pragma unroll 4
        for (int q4 = 0; q4 < CLEN/4; q4++) {
            float4 uu = uc4[q4];
            ull p = mul2(B0v, pk(uu.w, uu.w));
            p = fma2(B1v, pk(uu.z, uu.z), p);
            p = fma2(B2v, pk(uu.y, uu.y), p);
            p = fma2(B3v, pk(uu.x, uu.x), p);
            ull t = fma2(A4RR, X, p);
            X = fma2(A4IN, Xs, t);
            float xr_, xi_; upk(X, xr_, xi_);
            Xs = pk(xi_, xr_);
        }
        float xr_, xi_; upk(X, xr_, xi_);
        carry[wid*64 + lane]      = xr_;
        carry[wid*64 + 32 + lane] = xi_;
    }
    __syncthreads();

    // ---- phase 2: warp 0 prefix-combines carries with dA^CLEN ----
    if (wid == 0) {
        float pr = a4r, pi = a4i;   // a^4 -> a^512 via 7 squarings
        #pragma unroll
        for (int k = 0; k < 7; k++) { float t = pr*pr - pi*pi; pi = 2.f*pr*pi; pr = t; }
        float Xr = 0.f, Xi = 0.f;
        #pragma unroll
        for (int s = 0; s < NCH; s++) {
            initv[s*64 + lane]      = Xr;
            initv[s*64 + 32 + lane] = Xi;
            if (s < NCH-1) {
                float cr_ = carry[s*64 + lane];
                float ci_ = carry[s*64 + 32 + lane];
                float nXr = fmaf(pr, Xr, fmaf(-pi, Xi, cr_));
                float nXi = fmaf(pi, Xr, fmaf( pr, Xi, ci_));
                Xr = nXr; Xi = nXi;
            }
        }
    }
    __syncthreads();

    // ---- phase 3: rescan with true init (packed), emit gelu(y) ----
    float Dh = Dp[h];
    float xr = initv[wid*64 + lane];
    float xi = initv[wid*64 + 32 + lane];
    ull ARR = pk(ar, ar), AIN = pk(-ai, ai), DBv = pk(dbr, dbi);
    float* q    = qbase + wid * (32*33);
    float* gout = g_act + (size_t)bid * LL + base;

    #define PST(UV, SL) { \
        ull bb_ = mul2(DBv, pk((UV),(UV))); \
        ull tt_ = fma2(ARR, pk(xr, xi), bb_); \
        ull XX_ = fma2(AIN, pk(xi, xr), tt_); \
        upk(XX_, xr, xi); \
        q[(SL)*33 + lane] = fmaf(c2r, xr, -c2i*xi); }

    for (int t0 = 0; t0 < CLEN; t0 += 32) {
        const float4* up4 = (const float4*)(u_sh + base + t0);
        #pragma unroll
        for (int jj = 0; jj < 8; jj++) {
            float4 uu = up4[jj];
            PST(uu.x, jj*4+0)
            PST(uu.y, jj*4+1)
            PST(uu.z, jj*4+2)
            PST(uu.w, jj*4+3)
        }
        __syncwarp();
        float s = 0.f;
        #pragma unroll
        for (int n = 0; n < 32; n++) s += q[lane*33 + n];
        int l = base + t0 + lane;
        float uu  = u_sh[l];
        float upv = (l > 0) ? u_sh[l-1] : 0.f;
        s = fmaf(Dh, uu, s);              // D skip
        s = fmaf(dcb * uu, upv, s);       // liquid term
        gout[t0 + lane] = gelu_tanh(s);
        __syncwarp();
    }
    #undef PST
}

// ---------------- output linear: out = W @ gelu(y) + bias -----------------
// block tile: 128 (o) x 64 (l); per-thread 8o x 4l, acc packed over o-pairs
__global__ void __launch_bounds__(256) gemm_kernel(const float* __restrict__ W,
                                                   const float* __restrict__ bias,
                                                   float* __restrict__ out)
{
    __shared__ float Wsh[16][130];   // [k][o] (+pad, even stride for b64 LDS)
    __shared__ float Gsh[16][64];    // [k][l]

    int bx = blockIdx.x;            // l tile (64)
    int by = blockIdx.y;            // o tile (128)
    int b  = blockIdx.z;
    int tid = threadIdx.x;
    int tx = tid & 15, ty = tid >> 4;
    int o0 = by * 128, l0 = bx * 64;
    const float* gact = g_act + (size_t)b * HH * LL;

    ull acc[4][4];
    #pragma unroll
    for (int p = 0; p < 4; p++)
        #pragma unroll
        for (int j = 0; j < 4; j++) acc[p][j] = pk(0.f, 0.f);

    for (int k0 = 0; k0 < HH; k0 += 16) {
        // load W panel [o0..o0+127][k0..k0+15] transposed -> Wsh[k][o]
        #pragma unroll
        for (int i = 0; i < 2; i++) {
            int idx = tid + i * 256;         // 0..511
            int o_ = idx >> 2, kq = idx & 3;
            float4 wv = *(const float4*)&W[(size_t)(o0 + o_) * HH + k0 + kq*4];
            Wsh[kq*4+0][o_] = wv.x;
            Wsh[kq*4+1][o_] = wv.y;
            Wsh[kq*4+2][o_] = wv.z;
            Wsh[kq*4+3][o_] = wv.w;
        }
        // load G panel [k0..k0+15][l0..l0+63]
        {
            int kk = tid >> 4, ll = (tid & 15) * 4;
            *(float4*)&Gsh[kk][ll] =
                *(const float4*)&gact[(size_t)(k0 + kk) * LL + l0 + ll];
        }
        __syncthreads();

        #pragma unroll
        for (int k = 0; k < 16; k++) {
            float4 gv = *(const float4*)&Gsh[k][tx*4];
            ull gb0 = pk(gv.x, gv.x);
            ull gb1 = pk(gv.y, gv.y);
            ull gb2 = pk(gv.z, gv.z);
            ull gb3 = pk(gv.w, gv.w);
            #pragma unroll
            for (int p = 0; p < 4; p++) {
                ull wp = *(const ull*)&Wsh[k][ty*8 + 2*p];
                acc[p][0] = fma2(wp, gb0, acc[p][0]);
                acc[p][1] = fma2(wp, gb1, acc[p][1]);
                acc[p][2] = fma2(wp, gb2, acc[p][2]);
                acc[p][3] = fma2(wp, gb3, acc[p][3]);
            }
        }
        __syncthreads();
    }

    #pragma unroll
    for (int p = 0; p < 4; p++) {
        float r0[4], r1[4];
        #pragma unroll
        for (int j = 0; j < 4; j++) upk(acc[p][j], r0[j], r1[j]);
        int o = o0 + ty*8 + 2*p;
        float bv0 = bias[o], bv1 = bias[o+1];
        float4 v0, v1;
        v0.x = r0[0]+bv0; v0.y = r0[1]+bv0; v0.z = r0[2]+bv0; v0.w = r0[3]+bv0;
        v1.x = r1[0]+bv1; v1.y = r1[1]+bv1; v1.z = r1[2]+bv1; v1.w = r1[3]+bv1;
        *(float4*)&out[((size_t)(b * HH + o    )) * LL + l0 + tx*4] = v0;
        *(float4*)&out[((size_t)(b * HH + o + 1)) * LL + l0 + tx*4] = v1;
    }
}

// ---------------------------- launch --------------------------------------
extern "C" void kernel_launch(void* const* d_in, const int* in_sizes, int n_in,
                              void* d_out, int out_size)
{
    const float* u      = (const float*)d_in[0];
    const float* log_dt = (const float*)d_in[1];
    const float* w_re   = (const float*)d_in[2];
    const float* w_im   = (const float*)d_in[3];
    const float* B_re   = (const float*)d_in[4];
    const float* B_im   = (const float*)d_in[5];
    const float* C_re   = (const float*)d_in[6];
    const float* C_im   = (const float*)d_in[7];
    const float* D      = (const float*)d_in[8];
    const float* W      = (const float*)d_in[9];
    const float* bias   = (const float*)d_in[10];
    float* out = (float*)d_out;

    int smem = (LL + NCH*64*2 + 8*32*33) * (int)sizeof(float);   // 54272 B
    cudaFuncSetAttribute(scan_kernel, cudaFuncAttributeMaxDynamicSharedMemorySize, smem);
    scan_kernel<<<BB*HH, 256, smem>>>(u, log_dt, w_re, w_im, B_re, B_im,
                                      C_re, C_im, D);

    gemm_kernel<<<dim3(LL/64, HH/128, BB), 256>>>(W, bias, out);
}

// round 3
// speedup vs baseline: 1.2756x; 1.0360x over previous
#include <cuda_runtime.h>

#define HH   256
#define NN   32
#define LL   4096
#define BB   4
#define NCH  8
#define CLEN 512   // LL / NCH

typedef unsigned long long ull;

// ---------------- device scratch (no allocations allowed) ----------------
__device__ float g_act[(size_t)BB*HH*LL];      // gelu(y) activations

// ---------------- packed f32x2 helpers ----------------
__device__ __forceinline__ ull pk(float lo, float hi) {
    ull r;
    asm("mov.b64 %0, {%1, %2};" : "=l"(r)
        : "r"(__float_as_uint(lo)), "r"(__float_as_uint(hi)));
    return r;
}
__device__ __forceinline__ void upk(ull v, float& lo, float& hi) {
    unsigned a, b;
    asm("mov.b64 {%0, %1}, %2;" : "=r"(a), "=r"(b) : "l"(v));
    lo = __uint_as_float(a); hi = __uint_as_float(b);
}
__device__ __forceinline__ ull fma2(ull a, ull b, ull c) {
    ull d;
    asm("fma.rn.f32x2 %0, %1, %2, %3;" : "=l"(d) : "l"(a), "l"(b), "l"(c));
    return d;
}
__device__ __forceinline__ ull mul2(ull a, ull b) {
    ull d;
    asm("mul.rn.f32x2 %0, %1, %2;" : "=l"(d) : "l"(a), "l"(b));
    return d;
}

__device__ __forceinline__ float gelu_tanh(float x)
{
    // jax.nn.gelu(approximate=True)
    float x3 = x * x * x;
    float z  = 0.7978845608028654f * fmaf(0.044715f, x3, x);
    float e  = __expf(2.f * z);
    float t  = 1.f - __fdividef(2.f, e + 1.f);   // tanh(z)
    return 0.5f * x * (1.f + t);
}

__device__ __forceinline__ float warp_sum(float v) {
    #pragma unroll
    for (int m = 16; m >= 1; m >>= 1) v += __shfl_xor_sync(0xffffffffu, v, m);
    return v;
}

// ---------------- fused scan: params + chunked scan + D + liquid + gelu ---
__global__ void __launch_bounds__(256) scan_kernel(
    const float* __restrict__ u,
    const float* __restrict__ log_dt,
    const float* __restrict__ w_re, const float* __restrict__ w_im,
    const float* __restrict__ B_re, const float* __restrict__ B_im,
    const float* __restrict__ C_re, const float* __restrict__ C_im,
    const float* __restrict__ Dp)
{
    extern __shared__ float sh[];
    float* u_sh  = sh;                    // LL floats
    float* carry = sh + LL;               // NCH*64
    float* initv = carry + NCH*64;        // NCH*64
    float* qbase = initv + NCH*64;        // 8 warps * 32*33

    int bid  = blockIdx.x;                // = b*HH + h
    int h    = bid & (HH-1);
    int tid  = threadIdx.x;
    int wid  = tid >> 5, lane = tid & 31;

    // stage whole sequence u[b,h,:] in SMEM
    const float4* ub4  = (const float4*)(u + (size_t)bid * LL);
    float4*       ush4 = (float4*)u_sh;
    #pragma unroll
    for (int i = tid; i < LL/4; i += 256) ush4[i] = ub4[i];

    // ---- per-warp (redundant) parameter computation ----
    int pidx = (h << 5) + lane;
    float dt = __expf(log_dt[h]);
    float zr = 0.5f * dt * w_re[pidx];
    float zi = 0.5f * dt * w_im[pidx];
    float dr = 1.f - zr, di = -zi;
    float inv = 1.f / (dr*dr + di*di);
    float nr = 1.f + zr, ni = zi;
    float ar = (nr*dr + ni*di) * inv;
    float ai = (ni*dr - nr*di) * inv;
    float brf = dt * B_re[pidx], bif = dt * B_im[pidx];
    float dbr = (brf*dr + bif*di) * inv;
    float dbi = (bif*dr - brf*di) * inv;
    float c2r = 2.f * C_re[pidx];
    float c2i = 2.f * C_im[pidx];

    // powers a^2..a^4, b_k = a^k * b
    float a2r = ar*ar - ai*ai,     a2i = 2.f*ar*ai;
    float a3r = a2r*ar - a2i*ai,   a3i = a2r*ai + a2i*ar;
    float a4r = a2r*a2r - a2i*a2i, a4i = 2.f*a2r*a2i;
    float b1r = ar*dbr - ai*dbi,   b1i = ar*dbi + ai*dbr;
    float b2r = a2r*dbr - a2i*dbi, b2i = a2r*dbi + a2i*dbr;
    float b3r = a3r*dbr - a3i*dbi, b3i = a3r*dbi + a3i*dbr;

    // projection vectors v_k = c2 * a^k, k = 1..4
    float v1r = c2r*ar  - c2i*ai,  v1i = c2r*ai  + c2i*ar;
    float v2r = c2r*a2r - c2i*a2i, v2i = c2r*a2i + c2i*a2r;
    float v3r = c2r*a3r - c2i*a3i, v3i = c2r*a3i + c2i*a3r;
    float v4r = c2r*a4r - c2i*a4i, v4i = c2r*a4i + c2i*a4r;

    // FIR scalars g_s = sum_n Re(c2 * a^s * b),  s = 0..3
    float g0f = warp_sum(c2r*dbr - c2i*dbi);
    float g1f = warp_sum(c2r*b1r - c2i*b1i);
    float g2f = warp_sum(c2r*b2r - c2i*b2i);
    float g3f = warp_sum(c2r*b3r - c2i*b3i);
    // liquid scalar: dCB = (sum dB over 2N) * Re(sum C dB over 2N) = 2*s1*g0
    float s1  = warp_sum(dbr);
    float dcb = 2.f * s1 * g0f;

    ull B0v = pk(dbr, dbi), B1v = pk(b1r, b1i);
    ull B2v = pk(b2r, b2i), B3v = pk(b3r, b3i);
    ull A4RR = pk(a4r, a4r), A4IN = pk(-a4i, a4i);
    ull VA = pk(v1r, v2r), VBn = pk(-v1i, -v2i);
    ull VC = pk(v3r, v4r), VDn = pk(-v3i, -v4i);
    __syncthreads();

    int base = wid * CLEN;

    // ---- phase 1: chunk-local carry via Horner-4 (last warp's carry dead) ----
    if (wid < NCH-1) {
        ull X = pk(0.f, 0.f), Xs = pk(0.f, 0.f);
        const float4* uc4 = (const float4*)(u_sh + base);
        #pragma unroll 4
        for (int q4 = 0; q4 < CLEN/4; q4++) {
            float4 uu = uc4[q4];
            ull p = mul2(B0v, pk(uu.w, uu.w));
            p = fma2(B1v, pk(uu.z, uu.z), p);
            p = fma2(B2v, pk(uu.y, uu.y), p);
            p = fma2(B3v, pk(uu.x, uu.x), p);
            ull t = fma2(A4RR, X, p);
            X = fma2(A4IN, Xs, t);
            float xr_, xi_; upk(X, xr_, xi_);
            Xs = pk(xi_, xr_);
        }
        float xr_, xi_; upk(X, xr_, xi_);
        carry[wid*64 + lane]      = xr_;
        carry[wid*64 + 32 + lane] = xi_;
    }
    __syncthreads();

    // ---- phase 2: warp 0 prefix-combines carries with dA^CLEN ----
    if (wid == 0) {
        float pr = a4r, pi = a4i;   // a^4 -> a^512 via 7 squarings
        #pragma unroll
        for (int k = 0; k < 7; k++) { float t = pr*pr - pi*pi; pi = 2.f*pr*pi; pr = t; }
        float Xr = 0.f, Xi = 0.f;
        #pragma unroll
        for (int s = 0; s < NCH; s++) {
            initv[s*64 + lane]      = Xr;
            initv[s*64 + 32 + lane] = Xi;
            if (s < NCH-1) {
                float cr_ = carry[s*64 + lane];
                float ci_ = carry[s*64 + 32 + lane];
                float nXr = fmaf(pr, Xr, fmaf(-pi, Xi, cr_));
                float nXi = fmaf(pi, Xr, fmaf( pr, Xi, ci_));
                Xr = nXr; Xi = nXi;
            }
        }
    }
    __syncthreads();

    // ---- phase 3: Horner-4 advance + packed projections ----
    float Dh = Dp[h];
    float xr = initv[wid*64 + lane];        // x_{base-1}
    float xi = initv[wid*64 + 32 + lane];
    ull X = pk(xr, xi);
    float* q    = qbase + wid * (32*33);
    float* gout = g_act + (size_t)bid * LL + base;

    for (int t0 = 0; t0 < CLEN; t0 += 32) {
        const float4* up4 = (const float4*)(u_sh + base + t0);
        #pragma unroll
        for (int g = 0; g < 8; g++) {
            float4 uu = up4[g];
            // projections of x_{T-1}: y-state-part for t = T..T+3
            ull XR2 = pk(xr, xr), XI2 = pk(xi, xi);
            ull P01 = fma2(VA, XR2, mul2(VBn, XI2));
            ull P23 = fma2(VC, XR2, mul2(VDn, XI2));
            float p0, p1, p2, p3;
            upk(P01, p0, p1); upk(P23, p2, p3);
            q[(g*4+0)*33 + lane] = p0;
            q[(g*4+1)*33 + lane] = p1;
            q[(g*4+2)*33 + lane] = p2;
            q[(g*4+3)*33 + lane] = p3;
            // advance 4 steps: X <- a^4 X + sum a^s b u
            ull p = mul2(B0v, pk(uu.w, uu.w));
            p = fma2(B1v, pk(uu.z, uu.z), p);
            p = fma2(B2v, pk(uu.y, uu.y), p);
            p = fma2(B3v, pk(uu.x, uu.x), p);
            ull t = fma2(A4RR, X, p);
            X = fma2(A4IN, pk(xi, xr), t);
            upk(X, xr, xi);
        }
        __syncwarp();
        // cross-state reduction (row lane, stride 33 -> conflict-free)
        float s = 0.f;
        #pragma unroll
        for (int n = 0; n < 32; n++) s += q[lane*33 + n];
        int l = base + t0 + lane;
        int r = lane & 3;
        // FIR tail: sum_{s<=r} g_s u_{t-s}   (l >= r always)
        s = fmaf(g0f, u_sh[l], s);
        if (r > 0) s = fmaf(g1f, u_sh[l-1], s);
        if (r > 1) s = fmaf(g2f, u_sh[l-2], s);
        if (r > 2) s = fmaf(g3f, u_sh[l-3], s);
        float uu  = u_sh[l];
        float upv = (l > 0) ? u_sh[l-1] : 0.f;
        s = fmaf(Dh, uu, s);              // D skip
        s = fmaf(dcb * uu, upv, s);       // liquid term
        gout[t0 + lane] = gelu_tanh(s);
        __syncwarp();
    }
}

// ---------------- output linear: out = W @ gelu(y) + bias -----------------
// block tile 128o x 128l, 256 threads, per-thread 8o x 8l, KSTEP=16
#define KSTEP 16
__global__ void __launch_bounds__(256, 2) gemm_kernel(const float* __restrict__ W,
                                                      const float* __restrict__ bias,
                                                      float* __restrict__ out)
{
    __shared__ float Wsh[KSTEP][128];   // [k][o]
    __shared__ float Gsh[KSTEP][128];   // [k][l]

    int bx = blockIdx.x;            // l tile (128)
    int by = blockIdx.y;            // o tile (128)
    int b  = blockIdx.z;
    int tid = threadIdx.x;
    int tx = tid & 15, ty = tid >> 4;
    int o0 = by * 128, l0 = bx * 128;
    const float* gact = g_act + (size_t)b * HH * LL;

    ull acc[4][8];
    #pragma unroll
    for (int p = 0; p < 4; p++)
        #pragma unroll
        for (int j = 0; j < 8; j++) acc[p][j] = pk(0.f, 0.f);

    for (int k0 = 0; k0 < HH; k0 += KSTEP) {
        // W panel [o0..+127][k0..+15] -> transposed Wsh[k][o]
        #pragma unroll
        for (int i = 0; i < 2; i++) {
            int idx = tid + i * 256;         // 0..511
            int o_ = idx >> 2, kq = idx & 3;
            float4 wv = *(const float4*)&W[(size_t)(o0 + o_) * HH + k0 + kq*4];
            Wsh[kq*4+0][o_] = wv.x;
            Wsh[kq*4+1][o_] = wv.y;
            Wsh[kq*4+2][o_] = wv.z;
            Wsh[kq*4+3][o_] = wv.w;
        }
        // G panel [k0..+15][l0..+127]
        #pragma unroll
        for (int i = 0; i < 2; i++) {
            int idx = tid + i * 256;         // 0..511
            int kk = idx >> 5, ll = (idx & 31) * 4;
            *(float4*)&Gsh[kk][ll] =
                *(const float4*)&gact[(size_t)(k0 + kk) * LL + l0 + ll];
        }
        __syncthreads();

        #pragma unroll
        for (int k = 0; k < KSTEP; k++) {
            float4 ga = *(const float4*)&Gsh[k][tx*8];
            float4 gb = *(const float4*)&Gsh[k][tx*8 + 4];
            ull g_[8];
            g_[0] = pk(ga.x, ga.x); g_[1] = pk(ga.y, ga.y);
            g_[2] = pk(ga.z, ga.z); g_[3] = pk(ga.w, ga.w);
            g_[4] = pk(gb.x, gb.x); g_[5] = pk(gb.y, gb.y);
            g_[6] = pk(gb.z, gb.z); g_[7] = pk(gb.w, gb.w);
            #pragma unroll
            for (int p = 0; p < 4; p++) {
                ull wp = *(const ull*)&Wsh[k][ty*8 + 2*p];
                #pragma unroll
                for (int j = 0; j < 8; j++)
                    acc[p][j] = fma2(wp, g_[j], acc[p][j]);
            }
        }
        __syncthreads();
    }

    #pragma unroll
    for (int p = 0; p < 4; p++) {
        float r0[8], r1[8];
        #pragma unroll
        for (int j = 0; j < 8; j++) upk(acc[p][j], r0[j], r1[j]);
        int o = o0 + ty*8 + 2*p;
        float bv0 = bias[o], bv1 = bias[o+1];
        float4 v;
        size_t base0 = ((size_t)(b * HH + o    )) * LL + l0 + tx*8;
        size_t base1 = ((size_t)(b * HH + o + 1)) * LL + l0 + tx*8;
        v.x = r0[0]+bv0; v.y = r0[1]+bv0; v.z = r0[2]+bv0; v.w = r0[3]+bv0;
        *(float4*)&out[base0] = v;
        v.x = r0[4]+bv0; v.y = r0[5]+bv0; v.z = r0[6]+bv0; v.w = r0[7]+bv0;
        *(float4*)&out[base0 + 4] = v;
        v.x = r1[0]+bv1; v.y = r1[1]+bv1; v.z = r1[2]+bv1; v.w = r1[3]+bv1;
        *(float4*)&out[base1] = v;
        v.x = r1[4]+bv1; v.y = r1[5]+bv1; v.z = r1[6]+bv1; v.w = r1[7]+bv1;
        *(float4*)&out[base1 + 4] = v;
    }
}

// ---------------------------- launch --------------------------------------
extern "C" void kernel_launch(void* const* d_in, const int* in_sizes, int n_in,
                              void* d_out, int out_size)
{
    const float* u      = (const float*)d_in[0];
    const float* log_dt = (const float*)d_in[1];
    const float* w_re   = (const float*)d_in[2];
    const float* w_im   = (const float*)d_in[3];
    const float* B_re   = (const float*)d_in[4];
    const float* B_im   = (const float*)d_in[5];
    const float* C_re   = (const float*)d_in[6];
    const float* C_im   = (const float*)d_in[7];
    const float* D      = (const float*)d_in[8];
    const float* W      = (const float*)d_in[9];
    const float* bias   = (const float*)d_in[10];
    float* out = (float*)d_out;

    int smem = (LL + NCH*64*2 + 8*32*33) * (int)sizeof(float);   // 54272 B
    cudaFuncSetAttribute(scan_kernel, cudaFuncAttributeMaxDynamicSharedMemorySize, smem);
    scan_kernel<<<BB*HH, 256, smem>>>(u, log_dt, w_re, w_im, B_re, B_im,
                                      C_re, C_im, D);

    gemm_kernel<<<dim3(LL/128, HH/128, BB), 256>>>(W, bias, out);
}